// round 16
// baseline (speedup 1.0000x reference)
#include <cuda_runtime.h>
#include <cuda_bf16.h>
#include <math.h>
#include <stdint.h>

#define Nn   128
#define TCAP 31
#define T    30
#define CIN  1280
#define WD   512
#define HD   1024
#define VOC  10000
#define G4   4096   // 4*HD

// ---------------- static device scratch (no runtime allocation) -------------
__device__ __align__(16) float g_embT[VOC * WD];            // tf32 bits
__device__ __align__(16) float g_WxT[WD * G4];
__device__ __align__(16) float g_WhA[2 * HD * G4];          // [Wh; Wattn]
__device__ __align__(16) float g_WpT[CIN * HD];
__device__ __align__(16) unsigned g_WvP[(size_t)(HD / 2) * VOC]; // bf16 k-pairs
__device__ __align__(16) float g_imgT[2048 * CIN];          // images transposed, tf32
// activations
__device__ __align__(16) float g_hA[Nn * 2 * HD];           // [h | attn] tf32
__device__ __align__(16) unsigned g_hsB[(size_t)T * Nn * HD / 2]; // hs bf16 pairs, rows (t*N+n)
__device__ float g_c[Nn * HD];
__device__ float g_Aflat[Nn * HD * 16];                     // fp32 A_flat[n,h,p]
__device__ __align__(16) float g_Xpre[(size_t)Nn * T * G4]; // fp32 rows (n*T+t)
__device__ float g_gates[Nn * G4];
__device__ float g_logits[(size_t)T * Nn * VOC];
// software grid barrier state (zero-initialized; generation is monotonic
// across graph replays so no reset is required)
__device__ unsigned g_barArr;
__device__ unsigned g_barGen;

// ---------------------------------------------------------------------------
__global__ void zero_kernel(float* out) {
    if (threadIdx.x == 0) out[0] = 0.0f;
}

__device__ __forceinline__ uint32_t f2tf32(float f) {
    uint32_t u;
    asm("cvt.rna.tf32.f32 %0, %1;" : "=r"(u) : "f"(f));
    return u;
}
__device__ __forceinline__ float tfv(float f) { return __uint_as_float(f2tf32(f)); }

__device__ __forceinline__ void mma_tf32(float c[4], const uint32_t a[4], const uint32_t b[2]) {
    asm volatile(
        "mma.sync.aligned.m16n8k8.row.col.f32.tf32.tf32.f32 "
        "{%0,%1,%2,%3}, {%4,%5,%6,%7}, {%8,%9}, {%0,%1,%2,%3};"
        : "+f"(c[0]), "+f"(c[1]), "+f"(c[2]), "+f"(c[3])
        : "r"(a[0]), "r"(a[1]), "r"(a[2]), "r"(a[3]), "r"(b[0]), "r"(b[1]));
}
__device__ __forceinline__ void mma_bf16(float c[4], const uint32_t a[4], const uint32_t b[2]) {
    asm volatile(
        "mma.sync.aligned.m16n8k16.row.col.f32.bf16.bf16.f32 "
        "{%0,%1,%2,%3}, {%4,%5,%6,%7}, {%8,%9}, {%0,%1,%2,%3};"
        : "+f"(c[0]), "+f"(c[1]), "+f"(c[2]), "+f"(c[3])
        : "r"(a[0]), "r"(a[1]), "r"(a[2]), "r"(a[3]), "r"(b[0]), "r"(b[1]));
}

__device__ __forceinline__ uint32_t smaddr(const void* p) {
    return (uint32_t)__cvta_generic_to_shared(p);
}
__device__ __forceinline__ void cpa16(uint32_t d, const void* s, int sz) {
    asm volatile("cp.async.cg.shared.global [%0], [%1], 16, %2;" :: "r"(d), "l"(s), "r"(sz));
}

// ============================================================================
// One-time per-launch conversions
// ============================================================================
#define N_EMB  (VOC * WD)
#define N_WX   (WD * G4)
#define N_WH   (HD * G4)
#define N_WP   (CIN * HD)
#define N_CVT  (N_EMB + N_WX + 2 * N_WH + N_WP)

__global__ void cvt_weights(const float* __restrict__ We, const float* __restrict__ Wx,
                            const float* __restrict__ Wh, const float* __restrict__ Wa,
                            const float* __restrict__ Wp) {
    int i = blockIdx.x * blockDim.x + threadIdx.x;
    if (i >= N_CVT) return;
    if (i < N_EMB) { g_embT[i] = tfv(We[i]); return; }
    i -= N_EMB;
    if (i < N_WX) { g_WxT[i] = tfv(Wx[i]); return; }
    i -= N_WX;
    if (i < N_WH) { g_WhA[i] = tfv(Wh[i]); return; }
    i -= N_WH;
    if (i < N_WH) { g_WhA[N_WH + i] = tfv(Wa[i]); return; }
    i -= N_WH;
    g_WpT[i] = tfv(Wp[i]);
}

// W_vocab [k][n] -> bf16 k-pair packed [k/2][n]
__global__ void pack_wv(const float* __restrict__ Wv) {
    int n = blockIdx.x * blockDim.x + threadIdx.x;
    int k2 = blockIdx.y;
    if (n < VOC) {
        unsigned lo = __bfloat16_as_ushort(__float2bfloat16(Wv[(size_t)(2 * k2) * VOC + n]));
        unsigned hi = __bfloat16_as_ushort(__float2bfloat16(Wv[(size_t)(2 * k2 + 1) * VOC + n]));
        g_WvP[(size_t)k2 * VOC + n] = lo | (hi << 16);
    }
}

// images [n, c, p] -> imgT [(n*16+p), c] tf32, smem-tiled transpose. Block = n.
__global__ void imgT_kernel(const float* __restrict__ img) {
    __shared__ float tile[256][17];
    int n = blockIdx.x;
    for (int c0 = 0; c0 < CIN; c0 += 256) {
        for (int idx = threadIdx.x; idx < 256 * 16; idx += blockDim.x) {
            int cc = idx >> 4, p = idx & 15;
            tile[cc][p] = img[(size_t)n * CIN * 16 + (c0 + cc) * 16 + p];
        }
        __syncthreads();
        for (int idx = threadIdx.x; idx < 256 * 16; idx += blockDim.x) {
            int p = idx >> 8, cc = idx & 255;
            g_imgT[(size_t)(n * 16 + p) * CIN + c0 + cc] = tfv(tile[cc][p]);
        }
        __syncthreads();
    }
}

// ============================================================================
// tf32 GEMM, cp.async 3-stage. BM=128, BK=16, BN=128. 256 threads.
// MODE 0: Xpre  = gather(embT,cap) @ WxT + b       (3840 x 4096, K=512)
// MODE 3: Aflat = imgT @ WpT + b_proj (scatter)    (2048 x 1024, K=1280)
// ============================================================================
template<int MODE>
__global__ void __launch_bounds__(256)
gemm_tf32(const float* __restrict__ bias, const int* __restrict__ captions) {
    constexpr int BM = 128, BK = 16, BN = 128;
    constexpr int NT  = BN / 16;
    constexpr int WCW = BN / 2;
    constexpr int KD  = (MODE == 0) ? WD : CIN;
    constexpr int LDB = (MODE == 3) ? HD : G4;
    constexpr int NIT = KD / BK;
    constexpr int AS = 20, BS = BN + 8;

    __shared__ __align__(16) float As[3][BM][AS];
    __shared__ __align__(16) float Bs[3][BK][BS];

    const float* Ab = (MODE == 0) ? g_embT : g_imgT;
    const float* Bb = (MODE == 0) ? g_WxT  : g_WpT;

    const int tid = threadIdx.x;
    const int rowBase = blockIdx.y * BM;
    const int colBase = blockIdx.x * BN;
    const int wid = tid >> 5, lane = tid & 31;
    const int gid = lane >> 2, tig = lane & 3;
    const int wr = wid & 3, wc = wid >> 2;

    const int ar = tid >> 1, ak = (tid & 1) * 8;
    const float* aRow;
    if (MODE == 0) {
        int r = rowBase + ar;
        aRow = Ab + (size_t)captions[(r / T) * TCAP + (r % T)] * WD;
    } else {
        aRow = Ab + (size_t)(rowBase + ar) * KD;
    }
    const int bk = tid >> 4;
    const int bc = (tid & 15) * 8;

    auto issue = [&](int it) {
        int st = it % 3;
        int k0 = it * BK;
        uint32_t ad = smaddr(&As[st][ar][ak]);
        const float* as = aRow + k0 + ak;
        cpa16(ad, as, 16);
        cpa16(ad + 16, as + 4, 16);
        uint32_t bd = smaddr(&Bs[st][bk][bc]);
        const float* bs = Bb + (size_t)(k0 + bk) * LDB + colBase + bc;
        cpa16(bd, bs, 16);
        cpa16(bd + 16, bs + 4, 16);
        asm volatile("cp.async.commit_group;");
    };

    float c[2][NT][4] = {};
    issue(0);
    issue(1);

    for (int it = 0; it < NIT; ++it) {
        asm volatile("cp.async.wait_group 1;");
        __syncthreads();
        if (it + 2 < NIT) issue(it + 2);
        int st = it % 3;
#pragma unroll
        for (int ks = 0; ks < BK; ks += 8) {
            uint32_t a[2][4];
#pragma unroll
            for (int mt = 0; mt < 2; mt++) {
                int rA = wr * 32 + mt * 16 + gid;
                a[mt][0] = __float_as_uint(As[st][rA][ks + tig]);
                a[mt][1] = __float_as_uint(As[st][rA + 8][ks + tig]);
                a[mt][2] = __float_as_uint(As[st][rA][ks + tig + 4]);
                a[mt][3] = __float_as_uint(As[st][rA + 8][ks + tig + 4]);
            }
            uint32_t bf[NT][2];
#pragma unroll
            for (int nt = 0; nt < NT; nt++) {
                int cB = wc * WCW + nt * 8 + gid;
                bf[nt][0] = __float_as_uint(Bs[st][ks + tig][cB]);
                bf[nt][1] = __float_as_uint(Bs[st][ks + tig + 4][cB]);
            }
#pragma unroll
            for (int mt = 0; mt < 2; mt++)
#pragma unroll
                for (int nt = 0; nt < NT; nt++)
                    mma_tf32(c[mt][nt], a[mt], bf[nt]);
        }
        __syncthreads();
    }

    // ---- epilogue ----
#pragma unroll
    for (int mt = 0; mt < 2; mt++) {
        int r0 = rowBase + wr * 32 + mt * 16 + gid;
#pragma unroll
        for (int nt = 0; nt < NT; nt++) {
            int col = colBase + wc * WCW + nt * 8 + tig * 2;
            float v0 = c[mt][nt][0], v1 = c[mt][nt][1];
            float v2 = c[mt][nt][2], v3 = c[mt][nt][3];
            if (MODE == 0) {
                float b0 = bias[col], b1 = bias[col + 1];
                size_t o0 = (size_t)r0 * G4 + col;
                size_t o1 = (size_t)(r0 + 8) * G4 + col;
                g_Xpre[o0] = v0 + b0;  g_Xpre[o0 + 1] = v1 + b1;
                g_Xpre[o1] = v2 + b0;  g_Xpre[o1 + 1] = v3 + b1;
            } else {
                int n0 = r0 >> 4, p0 = r0 & 15;
                int n1 = (r0 + 8) >> 4, p1 = (r0 + 8) & 15;
                float b0 = bias[col], b1 = bias[col + 1];
                g_Aflat[n0 * (HD * 16) + col * 16 + p0]       = v0 + b0;
                g_Aflat[n0 * (HD * 16) + (col + 1) * 16 + p0] = v1 + b1;
                g_Aflat[n1 * (HD * 16) + col * 16 + p1]       = v2 + b0;
                g_Aflat[n1 * (HD * 16) + (col + 1) * 16 + p1] = v3 + b1;
            }
        }
    }
}

// ============================================================================
// bf16 logits GEMM: logits = hsB @ WvP + b_vocab   (3840 x 10000, K=1024)
// ============================================================================
__global__ void __launch_bounds__(256)
gemm_bf16_logits(const float* __restrict__ bias) {
    constexpr int BM = 128, BN = 128, BKP = 16;
    constexpr int NT = 8, WCW = 64;
    constexpr int KP = HD / 2;
    constexpr int NIT = KP / BKP;
    constexpr int AS = 20, BS = BN + 8;

    __shared__ __align__(16) uint32_t As[3][BM][AS];
    __shared__ __align__(16) uint32_t Bs[3][BKP][BS];

    const int tid = threadIdx.x;
    const int rowBase = blockIdx.y * BM;
    const int colBase = blockIdx.x * BN;
    const int wid = tid >> 5, lane = tid & 31;
    const int gid = lane >> 2, tig = lane & 3;
    const int wr = wid & 3, wc = wid >> 2;

    const int ar = tid >> 1, ak = (tid & 1) * 8;
    const unsigned* aRow = g_hsB + (size_t)(rowBase + ar) * KP;
    const int bk = tid >> 4, bc = (tid & 15) * 8;

    auto issue = [&](int it) {
        int st = it % 3;
        int kp = it * BKP;
        uint32_t ad = smaddr(&As[st][ar][ak]);
        const unsigned* as = aRow + kp + ak;
        cpa16(ad, as, 16);
        cpa16(ad + 16, as + 4, 16);
        uint32_t bd = smaddr(&Bs[st][bk][bc]);
        const unsigned* bs = g_WvP + (size_t)(kp + bk) * VOC + colBase + bc;
        cpa16(bd, bs, (colBase + bc + 4 <= VOC) ? 16 : 0);
        cpa16(bd + 16, bs + 4, (colBase + bc + 8 <= VOC) ? 16 : 0);
        asm volatile("cp.async.commit_group;");
    };

    float c[2][NT][4] = {};
    issue(0);
    issue(1);

    for (int it = 0; it < NIT; ++it) {
        asm volatile("cp.async.wait_group 1;");
        __syncthreads();
        if (it + 2 < NIT) issue(it + 2);
        int st = it % 3;
#pragma unroll
        for (int ks = 0; ks < BKP; ks += 8) {
            uint32_t a[2][4];
#pragma unroll
            for (int mt = 0; mt < 2; mt++) {
                int rA = wr * 32 + mt * 16 + gid;
                a[mt][0] = As[st][rA][ks + tig];
                a[mt][1] = As[st][rA + 8][ks + tig];
                a[mt][2] = As[st][rA][ks + tig + 4];
                a[mt][3] = As[st][rA + 8][ks + tig + 4];
            }
            uint32_t bf[NT][2];
#pragma unroll
            for (int nt = 0; nt < NT; nt++) {
                int cB = wc * WCW + nt * 8 + gid;
                bf[nt][0] = Bs[st][ks + tig][cB];
                bf[nt][1] = Bs[st][ks + tig + 4][cB];
            }
#pragma unroll
            for (int mt = 0; mt < 2; mt++)
#pragma unroll
                for (int nt = 0; nt < NT; nt++)
                    mma_bf16(c[mt][nt], a[mt], bf[nt]);
        }
        __syncthreads();
    }

#pragma unroll
    for (int mt = 0; mt < 2; mt++) {
        int r0 = rowBase + wr * 32 + mt * 16 + gid;
#pragma unroll
        for (int nt = 0; nt < NT; nt++) {
            int col = colBase + wc * WCW + nt * 8 + tig * 2;
            if (col < VOC) {
                float b0 = bias[col];
                g_logits[(size_t)r0 * VOC + col]       = c[mt][nt][0] + b0;
                g_logits[(size_t)(r0 + 8) * VOC + col] = c[mt][nt][2] + b0;
            }
            if (col + 1 < VOC) {
                float b1 = bias[col + 1];
                g_logits[(size_t)r0 * VOC + col + 1]       = c[mt][nt][1] + b1;
                g_logits[(size_t)(r0 + 8) * VOC + col + 1] = c[mt][nt][3] + b1;
            }
        }
    }
}

// ============================================================================
// h0 + first attention (1024 threads, block = sample)
// ============================================================================
__device__ __forceinline__ void attn_body_1024(int n, const float* sh_h, float* sh_s, int tid) {
    int w = tid >> 5, lane = tid & 31;
    const float* A = &g_Aflat[n * HD * 16];
    if (w < 16) {
        float s = 0.f;
        for (int h = lane; h < HD; h += 32) s += sh_h[h] * A[h * 16 + w];
#pragma unroll
        for (int o = 16; o > 0; o >>= 1) s += __shfl_down_sync(0xffffffffu, s, o);
        if (lane == 0) sh_s[w] = s * 0.03125f;
    }
    __syncthreads();
    if (tid < 32) {
        float v = (lane < 16) ? sh_s[lane] : -INFINITY;
        float m = v;
#pragma unroll
        for (int o = 16; o > 0; o >>= 1) m = fmaxf(m, __shfl_xor_sync(0xffffffffu, m, o));
        float e = (lane < 16) ? __expf(v - m) : 0.f;
        float sum = e;
#pragma unroll
        for (int o = 16; o > 0; o >>= 1) sum += __shfl_xor_sync(0xffffffffu, sum, o);
        if (lane < 16) sh_s[lane] = e / sum;
    }
    __syncthreads();
    const float* ap = &A[tid * 16];
    float r = 0.f;
#pragma unroll
    for (int p = 0; p < 16; p++) r += ap[p] * sh_s[p];
    g_hA[n * 2 * HD + HD + tid] = tfv(r);
}

__global__ void h0_attn_kernel() {
    int n = blockIdx.x;
    int tid = threadIdx.x;
    __shared__ float sh_h[HD];
    __shared__ float sh_s[16];
    const float* a = &g_Aflat[(n * HD + tid) * 16];
    float s = 0.f;
#pragma unroll
    for (int p = 0; p < 16; p++) s += a[p];
    s *= (1.0f / 16.0f);
    g_c[n * HD + tid] = s;
    g_hA[n * 2 * HD + tid] = tfv(s);
    sh_h[tid] = s;
    __syncthreads();
    attn_body_1024(n, sh_h, sh_s, tid);
}

__device__ __forceinline__ float sigf(float x) { return 1.0f / (1.0f + __expf(-x)); }

// ============================================================================
// PERSISTENT recurrence kernel: 128 CTAs x 256 threads, whole T-step loop.
// Per step: phase A = gates GEMM tile (BM=128, BN=32, K=2048, cp.async),
// grid barrier, phase C = lstm+attn for sample == blockIdx.x, grid barrier.
// All 128 CTAs are co-resident (128 <= 148 SMs, 1 CTA/SM), so the software
// barrier cannot deadlock.
// ============================================================================
__device__ __forceinline__ void grid_sync() {
    __syncthreads();
    if (threadIdx.x == 0) {
        unsigned gen = *(volatile unsigned*)&g_barGen;   // read BEFORE arrive
        __threadfence();                                  // release prior writes
        if (atomicAdd(&g_barArr, 1u) == gridDim.x - 1) {
            atomicExch(&g_barArr, 0u);
            __threadfence();
            atomicAdd(&g_barGen, 1u);
        } else {
            while (*(volatile unsigned*)&g_barGen == gen) __nanosleep(64);
        }
        __threadfence();                                  // acquire
    }
    __syncthreads();
}

__global__ void __launch_bounds__(256)
step_persistent() {
    constexpr int BM = 128, BK = 16, BN = 32;
    constexpr int NT = 2, WCW = 16;
    constexpr int KD = 2 * HD;
    constexpr int NIT = KD / BK;            // 128
    constexpr int AS = 20, BS = BN + 8;

    __shared__ __align__(16) float As[3][BM][AS];   // 30720 B
    __shared__ __align__(16) float Bs[3][BK][BS];   // 7680 B
    __shared__ float sh_h[HD];                       // 4096 B
    __shared__ float sh_s[16];

    const int tid = threadIdx.x;
    const int cta = blockIdx.x;             // 0..127
    const int colBase = cta * BN;
    const int n = cta;                      // sample for phase C
    const int wid = tid >> 5, lane = tid & 31;
    const int gid = lane >> 2, tig = lane & 3;
    const int wr = wid & 3, wc = wid >> 2;

    const int ar = tid >> 1, ak = (tid & 1) * 8;
    const float* aRow = g_hA + (size_t)ar * KD;
    const int bk = tid >> 3;
    const int bc = (tid & 7) * 4;
    const bool bact = (tid < 128);

    for (int t = 0; t < T; ++t) {
        // ---------------- phase A: gates tile ----------------
        auto issue = [&](int it) {
            int st = it % 3;
            int k0 = it * BK;
            uint32_t ad = smaddr(&As[st][ar][ak]);
            const float* as = aRow + k0 + ak;
            cpa16(ad, as, 16);
            cpa16(ad + 16, as + 4, 16);
            if (bact) {
                uint32_t bd = smaddr(&Bs[st][bk][bc]);
                const float* bs = g_WhA + (size_t)(k0 + bk) * G4 + colBase + bc;
                cpa16(bd, bs, 16);
            }
            asm volatile("cp.async.commit_group;");
        };

        float c[2][NT][4] = {};
        issue(0);
        issue(1);

        for (int it = 0; it < NIT; ++it) {
            asm volatile("cp.async.wait_group 1;");
            __syncthreads();
            if (it + 2 < NIT) issue(it + 2);
            int st = it % 3;
#pragma unroll
            for (int ks = 0; ks < BK; ks += 8) {
                uint32_t a[2][4];
#pragma unroll
                for (int mt = 0; mt < 2; mt++) {
                    int rA = wr * 32 + mt * 16 + gid;
                    a[mt][0] = __float_as_uint(As[st][rA][ks + tig]);
                    a[mt][1] = __float_as_uint(As[st][rA + 8][ks + tig]);
                    a[mt][2] = __float_as_uint(As[st][rA][ks + tig + 4]);
                    a[mt][3] = __float_as_uint(As[st][rA + 8][ks + tig + 4]);
                }
                uint32_t bf[NT][2];
#pragma unroll
                for (int nt = 0; nt < NT; nt++) {
                    int cB = wc * WCW + nt * 8 + gid;
                    bf[nt][0] = __float_as_uint(Bs[st][ks + tig][cB]);
                    bf[nt][1] = __float_as_uint(Bs[st][ks + tig + 4][cB]);
                }
#pragma unroll
                for (int mt = 0; mt < 2; mt++)
#pragma unroll
                    for (int nt = 0; nt < NT; nt++)
                        mma_tf32(c[mt][nt], a[mt], bf[nt]);
            }
            __syncthreads();
        }

#pragma unroll
        for (int mt = 0; mt < 2; mt++) {
            int r0 = wr * 32 + mt * 16 + gid;
#pragma unroll
            for (int nt = 0; nt < NT; nt++) {
                int col = colBase + wc * WCW + nt * 8 + tig * 2;
                size_t x0 = ((size_t)r0 * T + t) * G4 + col;
                size_t x1 = ((size_t)(r0 + 8) * T + t) * G4 + col;
                g_gates[r0 * G4 + col]           = c[mt][nt][0] + g_Xpre[x0];
                g_gates[r0 * G4 + col + 1]       = c[mt][nt][1] + g_Xpre[x0 + 1];
                g_gates[(r0 + 8) * G4 + col]     = c[mt][nt][2] + g_Xpre[x1];
                g_gates[(r0 + 8) * G4 + col + 1] = c[mt][nt][3] + g_Xpre[x1 + 1];
            }
        }

        grid_sync();   // gates complete, visible to all

        // ---------------- phase C: lstm + next-step attention -------------
        const float* gr = &g_gates[n * G4];
        for (int h = tid; h < HD; h += 256) {
            float gi = gr[h], gf = gr[h + HD], go = gr[h + 2 * HD], gg = gr[h + 3 * HD];
            float cc = sigf(gf) * g_c[n * HD + h] + sigf(gi) * tanhf(gg);
            float hh = sigf(go) * tanhf(cc);
            g_c[n * HD + h] = cc;
            g_hA[n * 2 * HD + h] = tfv(hh);
            ((__nv_bfloat16*)g_hsB)[((size_t)t * Nn + n) * HD + h] = __float2bfloat16(hh);
            sh_h[h] = hh;
        }
        __syncthreads();

        if (t < T - 1) {
            const float* A = &g_Aflat[n * HD * 16];
            // scores: 8 warps x 2 p's
            for (int pp = wid; pp < 16; pp += 8) {
                float s = 0.f;
                for (int h = lane; h < HD; h += 32) s += sh_h[h] * A[h * 16 + pp];
#pragma unroll
                for (int o = 16; o > 0; o >>= 1) s += __shfl_down_sync(0xffffffffu, s, o);
                if (lane == 0) sh_s[pp] = s * 0.03125f;
            }
            __syncthreads();
            if (tid < 32) {
                float v = (lane < 16) ? sh_s[lane] : -INFINITY;
                float m = v;
#pragma unroll
                for (int o = 16; o > 0; o >>= 1) m = fmaxf(m, __shfl_xor_sync(0xffffffffu, m, o));
                float e = (lane < 16) ? __expf(v - m) : 0.f;
                float sum = e;
#pragma unroll
                for (int o = 16; o > 0; o >>= 1) sum += __shfl_xor_sync(0xffffffffu, sum, o);
                if (lane < 16) sh_s[lane] = e / sum;
            }
            __syncthreads();
            for (int h = tid; h < HD; h += 256) {
                const float* ap = &A[h * 16];
                float r = 0.f;
#pragma unroll
                for (int p = 0; p < 16; p++) r += ap[p] * sh_s[p];
                g_hA[n * 2 * HD + HD + h] = tfv(r);
            }
        }

        grid_sync();   // hA ready for next step's phase A
    }
}

// loss: per-row logsumexp + masked NLL accumulated into out[0]
__global__ void loss_kernel(const int* __restrict__ captions, float* out) {
    int r = blockIdx.x;               // r = t*N + n
    __shared__ float red[256];
    const float* row = &g_logits[(size_t)r * VOC];
    int tid = threadIdx.x;

    float m = -INFINITY;
    for (int v = tid; v < VOC; v += 256) m = fmaxf(m, row[v]);
    red[tid] = m;
    __syncthreads();
    for (int s = 128; s > 0; s >>= 1) {
        if (tid < s) red[tid] = fmaxf(red[tid], red[tid + s]);
        __syncthreads();
    }
    float mx = red[0];
    __syncthreads();

    float se = 0.f;
    for (int v = tid; v < VOC; v += 256) se += expf(row[v] - mx);
    red[tid] = se;
    __syncthreads();
    for (int s = 128; s > 0; s >>= 1) {
        if (tid < s) red[tid] += red[tid + s];
        __syncthreads();
    }

    if (tid == 0) {
        int t = r / Nn, n = r % Nn;
        int tgt = captions[n * TCAP + t + 1];
        if (tgt != 0) {
            float nll = logf(red[0]) + mx - row[tgt];
            atomicAdd(out, nll * (1.0f / Nn));
        }
    }
}

// ============================================================================
extern "C" void kernel_launch(void* const* d_in, const int* in_sizes, int n_in,
                              void* d_out, int out_size) {
    const float* images   = (const float*)d_in[0];
    const int*   captions = (const int*)  d_in[1];
    const float* W_embed  = (const float*)d_in[2];
    const float* W_proj   = (const float*)d_in[3];
    const float* b_proj   = (const float*)d_in[4];
    const float* Wx       = (const float*)d_in[5];
    const float* Wh       = (const float*)d_in[6];
    const float* Wattn    = (const float*)d_in[7];
    const float* b        = (const float*)d_in[8];
    const float* W_vocab  = (const float*)d_in[9];
    const float* b_vocab  = (const float*)d_in[10];
    float* out = (float*)d_out;

    zero_kernel<<<1, 32>>>(out);
    cvt_weights<<<(N_CVT + 255) / 256, 256>>>(W_embed, Wx, Wh, Wattn, W_proj);
    pack_wv<<<dim3((VOC + 255) / 256, HD / 2), 256>>>(W_vocab);
    imgT_kernel<<<Nn, 256>>>(images);

    // proj: 2048 x 1024, K=1280
    gemm_tf32<3><<<dim3(HD / 128, 2048 / 128), 256>>>(b_proj, nullptr);
    h0_attn_kernel<<<Nn, 1024>>>();
    // Xpre: 3840 x 4096, K=512
    gemm_tf32<0><<<dim3(G4 / 128, (Nn * T) / 128), 256>>>(b, captions);

    // whole recurrence in ONE persistent kernel
    step_persistent<<<Nn, 256>>>();

    // logits: 3840 x 10000, K=1024, bf16
    gemm_bf16_logits<<<dim3((VOC + 127) / 128, (Nn * T) / 128), 256>>>(b_vocab);
    loss_kernel<<<T * Nn, 256>>>(captions, out);
}